// round 9
// baseline (speedup 1.0000x reference)
#include <cuda_runtime.h>

// TTT_57174604644761: B=2, S=2048, H=16, D=64, fp32.
// Per (b,h):  A1 = tril(Q K^T); O2 = A1 K; A2 = tril(O2 K^T); Out = (2*A1 - A2) V
// Identity: 2*tril(QK^T) - tril(O2 K^T) = tril((2Q - O2) K^T)  =>  pass 2 does one
// score matmul against W = 2Q - O2.
// All inner products use Blackwell packed fp32 FMA (fma.rn.f32x2 -> FFMA2),
// 2 IEEE fp32 FMAs per instruction; numerics identical to scalar fp32.
// qkv layout: [B, S, 3, H, D] fp32.  out: [B, S, H, D] fp32.

#define SLEN 2048
#define NH   16
#define NB   2
#define DIM  64
#define BT   128            // query/key tile rows
#define PAD_D 68            // padded row stride for [128][64] tiles (floats)
#define PAD_S 132           // padded row stride for [128][128] tile (floats)
#define NTHREADS 256

// smem: Qs(->Ws), Ks, Vs : [BT][PAD_D]; Ss : [BT][PAD_S]
#define SMEM_FLOATS (3 * BT * PAD_D + BT * PAD_S)
#define SMEM_BYTES  (SMEM_FLOATS * 4)

typedef unsigned long long u64;

// ---- packed f32x2 helpers (sm_103a) ----
__device__ __forceinline__ u64 pk2(float lo, float hi) {
    u64 r;
    asm("mov.b64 %0, {%1, %2};"
        : "=l"(r) : "r"(__float_as_uint(lo)), "r"(__float_as_uint(hi)));
    return r;
}
__device__ __forceinline__ void upk2(float& lo, float& hi, u64 p) {
    unsigned ulo, uhi;
    asm("mov.b64 {%0, %1}, %2;" : "=r"(ulo), "=r"(uhi) : "l"(p));
    lo = __uint_as_float(ulo);
    hi = __uint_as_float(uhi);
}
__device__ __forceinline__ void fma2(u64& c, u64 a, u64 b) {
    asm("fma.rn.f32x2 %0, %1, %2, %0;" : "+l"(c) : "l"(a), "l"(b));
}

extern __shared__ float smem[];

__global__ __launch_bounds__(NTHREADS, 1)
void ttt_kernel(const float* __restrict__ qkv, float* __restrict__ out) {
    const int i   = blockIdx.x;   // query block index (0..15)
    const int h   = blockIdx.y;
    const int b   = blockIdx.z;
    const int tid = threadIdx.x;
    const int tx  = tid & 15;     // 0..15
    const int ty  = tid >> 4;     // 0..15

    float* Qs  = smem;                    // Q in pass 1, W = 2Q - O2 in pass 2
    float* Ks  = Qs  + BT * PAD_D;
    float* Vs  = Ks  + BT * PAD_D;
    float* Ss  = Vs  + BT * PAD_D;

    const long rowstride = 3L * NH * DIM;
    const float* qbase = qkv + (long)b * SLEN * rowstride + (long)(0 * NH + h) * DIM;
    const float* kbase = qkv + (long)b * SLEN * rowstride + (long)(1 * NH + h) * DIM;
    const float* vbase = qkv + (long)b * SLEN * rowstride + (long)(2 * NH + h) * DIM;

    const int t0 = i * BT;

    // ---- load Q tile ----
    for (int idx = tid; idx < BT * 16; idx += NTHREADS) {
        int r = idx >> 4, c4 = idx & 15;
        *(float4*)(&Qs[r * PAD_D + c4 * 4]) =
            *(const float4*)(qbase + (long)(t0 + r) * rowstride + c4 * 4);
    }

    // =================== PASS 1: O2 = tril(Q K^T) K ===================
    // o2acc2[u2][v]: rows paired (ty+32*u2, ty+32*u2+16), col tx+16*v
    u64 o2acc2[4][4];
    #pragma unroll
    for (int u2 = 0; u2 < 4; u2++)
        #pragma unroll
        for (int v = 0; v < 4; v++) o2acc2[u2][v] = 0ULL;

    for (int j = 0; j <= i; ++j) {
        __syncthreads();
        for (int idx = tid; idx < BT * 16; idx += NTHREADS) {
            int r = idx >> 4, c4 = idx & 15;
            *(float4*)(&Ks[r * PAD_D + c4 * 4]) =
                *(const float4*)(kbase + (long)(j * BT + r) * rowstride + c4 * 4);
        }
        __syncthreads();

        // S1 = Q K_j^T : acc2[u][v2] covers cols (tx+32*v2, tx+32*v2+16)
        u64 acc2[8][4];
        #pragma unroll
        for (int u = 0; u < 8; u++)
            #pragma unroll
            for (int v2 = 0; v2 < 4; v2++) acc2[u][v2] = 0ULL;

        #pragma unroll 4
        for (int d = 0; d < DIM; ++d) {
            u64 q2[8], k2[4];
            #pragma unroll
            for (int u = 0; u < 8; u++) {
                float q = Qs[(ty + 16 * u) * PAD_D + d];
                q2[u] = pk2(q, q);
            }
            #pragma unroll
            for (int v2 = 0; v2 < 4; v2++)
                k2[v2] = pk2(Ks[(tx + 32 * v2) * PAD_D + d],
                             Ks[(tx + 32 * v2 + 16) * PAD_D + d]);
            #pragma unroll
            for (int u = 0; u < 8; u++)
                #pragma unroll
                for (int v2 = 0; v2 < 4; v2++) fma2(acc2[u][v2], q2[u], k2[v2]);
        }

        // unpack, mask on diagonal block, store to Ss
        #pragma unroll
        for (int u = 0; u < 8; u++) {
            int r = ty + 16 * u;
            #pragma unroll
            for (int v2 = 0; v2 < 4; v2++) {
                float lo, hi;
                upk2(lo, hi, acc2[u][v2]);
                int c0 = tx + 32 * v2, c1 = c0 + 16;
                if (j == i) {
                    if (c0 > r) lo = 0.f;
                    if (c1 > r) hi = 0.f;
                }
                Ss[r * PAD_S + c0] = lo;
                Ss[r * PAD_S + c1] = hi;
            }
        }
        __syncthreads();

        // O2 += S1 K_j : rows paired along u
        #pragma unroll 4
        for (int s = 0; s < BT; ++s) {
            u64 a2[4], k2b[4];
            #pragma unroll
            for (int u2 = 0; u2 < 4; u2++)
                a2[u2] = pk2(Ss[(ty + 32 * u2) * PAD_S + s],
                             Ss[(ty + 32 * u2 + 16) * PAD_S + s]);
            #pragma unroll
            for (int v = 0; v < 4; v++) {
                float kk = Ks[s * PAD_D + tx + 16 * v];
                k2b[v] = pk2(kk, kk);
            }
            #pragma unroll
            for (int u2 = 0; u2 < 4; u2++)
                #pragma unroll
                for (int v = 0; v < 4; v++) fma2(o2acc2[u2][v], a2[u2], k2b[v]);
        }
    }

    // ---- W = 2Q - O2, in place over Qs ----
    __syncthreads();
    #pragma unroll
    for (int u2 = 0; u2 < 4; u2++)
        #pragma unroll
        for (int v = 0; v < 4; v++) {
            float lo, hi;
            upk2(lo, hi, o2acc2[u2][v]);
            int r0 = ty + 32 * u2, r1 = r0 + 16, c = tx + 16 * v;
            Qs[r0 * PAD_D + c] = 2.f * Qs[r0 * PAD_D + c] - lo;
            Qs[r1 * PAD_D + c] = 2.f * Qs[r1 * PAD_D + c] - hi;
        }

    // =================== PASS 2: Out = tril(W K^T) V ===================
    u64 outacc2[4][4];
    #pragma unroll
    for (int u2 = 0; u2 < 4; u2++)
        #pragma unroll
        for (int v = 0; v < 4; v++) outacc2[u2][v] = 0ULL;

    for (int j = 0; j <= i; ++j) {
        __syncthreads();
        for (int idx = tid; idx < 2 * BT * 16; idx += NTHREADS) {
            int half = idx >= BT * 16;
            int id2 = idx - half * BT * 16;
            int r = id2 >> 4, c4 = id2 & 15;
            const float* src = half ? vbase : kbase;
            float* dst = half ? Vs : Ks;
            *(float4*)(&dst[r * PAD_D + c4 * 4]) =
                *(const float4*)(src + (long)(j * BT + r) * rowstride + c4 * 4);
        }
        __syncthreads();

        // A = W K_j^T
        u64 acc2[8][4];
        #pragma unroll
        for (int u = 0; u < 8; u++)
            #pragma unroll
            for (int v2 = 0; v2 < 4; v2++) acc2[u][v2] = 0ULL;

        #pragma unroll 4
        for (int d = 0; d < DIM; ++d) {
            u64 w2[8], k2[4];
            #pragma unroll
            for (int u = 0; u < 8; u++) {
                float w = Qs[(ty + 16 * u) * PAD_D + d];
                w2[u] = pk2(w, w);
            }
            #pragma unroll
            for (int v2 = 0; v2 < 4; v2++)
                k2[v2] = pk2(Ks[(tx + 32 * v2) * PAD_D + d],
                             Ks[(tx + 32 * v2 + 16) * PAD_D + d]);
            #pragma unroll
            for (int u = 0; u < 8; u++)
                #pragma unroll
                for (int v2 = 0; v2 < 4; v2++) fma2(acc2[u][v2], w2[u], k2[v2]);
        }

        #pragma unroll
        for (int u = 0; u < 8; u++) {
            int r = ty + 16 * u;
            #pragma unroll
            for (int v2 = 0; v2 < 4; v2++) {
                float lo, hi;
                upk2(lo, hi, acc2[u][v2]);
                int c0 = tx + 32 * v2, c1 = c0 + 16;
                if (j == i) {
                    if (c0 > r) lo = 0.f;
                    if (c1 > r) hi = 0.f;
                }
                Ss[r * PAD_S + c0] = lo;
                Ss[r * PAD_S + c1] = hi;
            }
        }
        __syncthreads();

        // Out += A V_j
        #pragma unroll 4
        for (int s = 0; s < BT; ++s) {
            u64 a2[4], v2b[4];
            #pragma unroll
            for (int u2 = 0; u2 < 4; u2++)
                a2[u2] = pk2(Ss[(ty + 32 * u2) * PAD_S + s],
                             Ss[(ty + 32 * u2 + 16) * PAD_S + s]);
            #pragma unroll
            for (int v = 0; v < 4; v++) {
                float vv = Vs[s * PAD_D + tx + 16 * v];
                v2b[v] = pk2(vv, vv);
            }
            #pragma unroll
            for (int u2 = 0; u2 < 4; u2++)
                #pragma unroll
                for (int v = 0; v < 4; v++) fma2(outacc2[u2][v], a2[u2], v2b[v]);
        }
    }

    // ---- write Out[b, t0+row, h, col] ----
    #pragma unroll
    for (int u2 = 0; u2 < 4; u2++) {
        int r0 = ty + 32 * u2, r1 = r0 + 16;
        float* ob0 = out + ((long)b * SLEN + (t0 + r0)) * (NH * DIM) + (long)h * DIM;
        float* ob1 = out + ((long)b * SLEN + (t0 + r1)) * (NH * DIM) + (long)h * DIM;
        #pragma unroll
        for (int v = 0; v < 4; v++) {
            float lo, hi;
            upk2(lo, hi, outacc2[u2][v]);
            ob0[tx + 16 * v] = lo;
            ob1[tx + 16 * v] = hi;
        }
    }
}

extern "C" void kernel_launch(void* const* d_in, const int* in_sizes, int n_in,
                              void* d_out, int out_size) {
    (void)in_sizes; (void)n_in; (void)out_size;
    const float* qkv = (const float*)d_in[0];
    float* out = (float*)d_out;

    static bool configured = false;
    if (!configured) {
        cudaFuncSetAttribute(ttt_kernel, cudaFuncAttributeMaxDynamicSharedMemorySize,
                             SMEM_BYTES);
        configured = true;
    }

    dim3 grid(SLEN / BT, NH, NB);   // (16, 16, 2)
    ttt_kernel<<<grid, NTHREADS, SMEM_BYTES>>>(qkv, out);
}

// round 11
// speedup vs baseline: 4.7551x; 4.7551x over previous
#include <cuda_runtime.h>

// TTT_57174604644761: B=2, S=2048, H=16, D=64, fp32.
// Per (b,h):  A1=tril(QK^T); O2=A1 K; A2=tril(O2 K^T); Out=(2A1-A2)V
// Identities:
//   2*tril(QK^T)-tril(O2 K^T) = tril((2Q-O2)K^T)   (W = 2Q-O2)
//   For row-block i:  O2_i = Q_i * Gsum_i + tril(Q_i K_i^T) K_i,
//                     Out_i = W_i * Hsum_i + tril(W_i K_i^T) V_i,
//   where Gsum_i = sum_{j<i} K_j^T K_j,  Hsum_i = sum_{j<i} K_j^T V_j  (64x64).
// => O(S) cross-block work instead of O(S^2). 3 launches:
//   A: per-block G_j,H_j -> device scratch; B: exclusive prefix scan over j
//      (in place; A rewrites raw values each replay, so graph-safe);
//   C: per (b,h,i) fully local solve (fp32, packed FFMA2).

#define SLEN 2048
#define NH   16
#define NB   2
#define DIM  64
#define BT   128
#define NBLK (SLEN / BT)      // 16
#define PAD_D 68
#define PAD_S 132
#define NTHREADS 256

#define GH_ELEMS (NB * NH * NBLK * DIM * DIM)
__device__ float g_G[GH_ELEMS];   // raw G_j, then exclusive prefix Gsum_i
__device__ float g_H[GH_ELEMS];

typedef unsigned long long u64;

__device__ __forceinline__ u64 pk2(float lo, float hi) {
    u64 r;
    asm("mov.b64 %0, {%1, %2};"
        : "=l"(r) : "r"(__float_as_uint(lo)), "r"(__float_as_uint(hi)));
    return r;
}
__device__ __forceinline__ void upk2(float& lo, float& hi, u64 p) {
    unsigned ulo, uhi;
    asm("mov.b64 {%0, %1}, %2;" : "=r"(ulo), "=r"(uhi) : "l"(p));
    lo = __uint_as_float(ulo);
    hi = __uint_as_float(uhi);
}
__device__ __forceinline__ void fma2(u64& c, u64 a, u64 b) {
    asm("fma.rn.f32x2 %0, %1, %2, %0;" : "+l"(c) : "l"(a), "l"(b));
}

extern __shared__ float smem[];

#define SMEM_A_BYTES (2 * BT * PAD_D * 4)
#define SMEM_C_FLOATS (3 * BT * PAD_D + BT * PAD_S + 2 * DIM * PAD_D)
#define SMEM_C_BYTES (SMEM_C_FLOATS * 4)

// ============ PHASE A: G_j = K_j^T K_j, H_j = K_j^T V_j ============
__global__ __launch_bounds__(NTHREADS, 1)
void phaseA(const float* __restrict__ qkv) {
    const int j = blockIdx.x, h = blockIdx.y, b = blockIdx.z;
    const int tid = threadIdx.x, tx = tid & 15, ty = tid >> 4;

    float* Ks = smem;
    float* Vs = Ks + BT * PAD_D;

    const long rowstride = 3L * NH * DIM;
    const float* kbase = qkv + (long)b * SLEN * rowstride + (long)(1 * NH + h) * DIM;
    const float* vbase = qkv + (long)b * SLEN * rowstride + (long)(2 * NH + h) * DIM;

    for (int idx = tid; idx < 2 * BT * 16; idx += NTHREADS) {
        int half = idx >= BT * 16;
        int id2 = idx - half * BT * 16;
        int r = id2 >> 4, c4 = id2 & 15;
        const float* src = half ? vbase : kbase;
        float* dst = half ? Vs : Ks;
        *(float4*)(&dst[r * PAD_D + c4 * 4]) =
            *(const float4*)(src + (long)(j * BT + r) * rowstride + c4 * 4);
    }
    __syncthreads();

    // rows r = ty+16u (u<4); col pairs p: (tx+32p, tx+32p+16), p<2
    u64 accG[4][2], accH[4][2];
    #pragma unroll
    for (int u = 0; u < 4; u++)
        #pragma unroll
        for (int p = 0; p < 2; p++) { accG[u][p] = 0ULL; accH[u][p] = 0ULL; }

    #pragma unroll 4
    for (int s = 0; s < BT; ++s) {
        u64 kr2[4], kc2[2], vc2[2];
        #pragma unroll
        for (int u = 0; u < 4; u++) {
            float kr = Ks[s * PAD_D + ty + 16 * u];
            kr2[u] = pk2(kr, kr);
        }
        #pragma unroll
        for (int p = 0; p < 2; p++) {
            kc2[p] = pk2(Ks[s * PAD_D + tx + 32 * p], Ks[s * PAD_D + tx + 32 * p + 16]);
            vc2[p] = pk2(Vs[s * PAD_D + tx + 32 * p], Vs[s * PAD_D + tx + 32 * p + 16]);
        }
        #pragma unroll
        for (int u = 0; u < 4; u++)
            #pragma unroll
            for (int p = 0; p < 2; p++) {
                fma2(accG[u][p], kr2[u], kc2[p]);
                fma2(accH[u][p], kr2[u], vc2[p]);
            }
    }

    const long base = ((long)(b * NH + h) * NBLK + j) * (DIM * DIM);
    #pragma unroll
    for (int u = 0; u < 4; u++) {
        int r = ty + 16 * u;
        #pragma unroll
        for (int p = 0; p < 2; p++) {
            float lo, hi;
            int c0 = tx + 32 * p, c1 = c0 + 16;
            upk2(lo, hi, accG[u][p]);
            g_G[base + r * DIM + c0] = lo;
            g_G[base + r * DIM + c1] = hi;
            upk2(lo, hi, accH[u][p]);
            g_H[base + r * DIM + c0] = lo;
            g_H[base + r * DIM + c1] = hi;
        }
    }
}

// ============ PHASE B: in-place exclusive prefix scan over j ============
__global__ __launch_bounds__(NTHREADS, 1)
void phaseB() {
    const long base = (long)blockIdx.x * NBLK * (DIM * DIM);
    for (int e = threadIdx.x; e < DIM * DIM; e += NTHREADS) {
        float runG = 0.f, runH = 0.f;
        #pragma unroll
        for (int j = 0; j < NBLK; ++j) {
            long idx = base + (long)j * (DIM * DIM) + e;
            float g = g_G[idx]; g_G[idx] = runG; runG += g;
            float hv = g_H[idx]; g_H[idx] = runH; runH += hv;
        }
    }
}

// ============ PHASE C: per (b,h,i) local solve ============
__global__ __launch_bounds__(NTHREADS, 1)
void phaseC(const float* __restrict__ qkv, float* __restrict__ out) {
    const int i = blockIdx.x, h = blockIdx.y, b = blockIdx.z;
    const int tid = threadIdx.x, tx = tid & 15, ty = tid >> 4;

    float* Qs = smem;                      // Q, then W = 2Q - O2
    float* Ks = Qs + BT * PAD_D;
    float* Vs = Ks + BT * PAD_D;
    float* Ss = Vs + BT * PAD_D;           // [BT][PAD_S]
    float* Gs = Ss + BT * PAD_S;           // [DIM][PAD_D]
    float* Hs = Gs + DIM * PAD_D;

    const long rowstride = 3L * NH * DIM;
    const float* qbase = qkv + (long)b * SLEN * rowstride + (long)(0 * NH + h) * DIM;
    const float* kbase = qkv + (long)b * SLEN * rowstride + (long)(1 * NH + h) * DIM;
    const float* vbase = qkv + (long)b * SLEN * rowstride + (long)(2 * NH + h) * DIM;
    const int t0 = i * BT;

    // ---- loads: Q_i, K_i, V_i ----
    for (int idx = tid; idx < 3 * BT * 16; idx += NTHREADS) {
        int which = idx / (BT * 16);
        int id2 = idx - which * (BT * 16);
        int r = id2 >> 4, c4 = id2 & 15;
        const float* src = (which == 0) ? qbase : (which == 1) ? kbase : vbase;
        float* dst = (which == 0) ? Qs : (which == 1) ? Ks : Vs;
        *(float4*)(&dst[r * PAD_D + c4 * 4]) =
            *(const float4*)(src + (long)(t0 + r) * rowstride + c4 * 4);
    }
    // ---- loads: Gsum_i, Hsum_i (exclusive prefix at block i) ----
    {
        const long gbase = ((long)(b * NH + h) * NBLK + i) * (DIM * DIM);
        for (int idx = tid; idx < 2 * DIM * 16; idx += NTHREADS) {
            int half = idx >= DIM * 16;
            int id2 = idx - half * DIM * 16;
            int r = id2 >> 4, c4 = id2 & 15;
            const float* src = half ? g_H : g_G;
            float* dst = half ? Hs : Gs;
            *(float4*)(&dst[r * PAD_D + c4 * 4]) =
                *(const float4*)(src + gbase + r * DIM + c4 * 4);
        }
    }
    __syncthreads();

    // ---- step 1: S1 = tril(Q K_i^T) -> Ss ----
    {
        u64 acc2[8][4];
        #pragma unroll
        for (int u = 0; u < 8; u++)
            #pragma unroll
            for (int v2 = 0; v2 < 4; v2++) acc2[u][v2] = 0ULL;
        #pragma unroll 4
        for (int d = 0; d < DIM; ++d) {
            u64 q2[8], k2[4];
            #pragma unroll
            for (int u = 0; u < 8; u++) {
                float q = Qs[(ty + 16 * u) * PAD_D + d];
                q2[u] = pk2(q, q);
            }
            #pragma unroll
            for (int v2 = 0; v2 < 4; v2++)
                k2[v2] = pk2(Ks[(tx + 32 * v2) * PAD_D + d],
                             Ks[(tx + 32 * v2 + 16) * PAD_D + d]);
            #pragma unroll
            for (int u = 0; u < 8; u++)
                #pragma unroll
                for (int v2 = 0; v2 < 4; v2++) fma2(acc2[u][v2], q2[u], k2[v2]);
        }
        #pragma unroll
        for (int u = 0; u < 8; u++) {
            int r = ty + 16 * u;
            #pragma unroll
            for (int v2 = 0; v2 < 4; v2++) {
                float lo, hi;
                upk2(lo, hi, acc2[u][v2]);
                int c0 = tx + 32 * v2, c1 = c0 + 16;
                if (c0 > r) lo = 0.f;
                if (c1 > r) hi = 0.f;
                Ss[r * PAD_S + c0] = lo;
                Ss[r * PAD_S + c1] = hi;
            }
        }
    }
    __syncthreads();

    // ---- step 2: O2 = S1*K_i + Q*Gsum ----
    u64 o2acc2[4][4];
    #pragma unroll
    for (int u2 = 0; u2 < 4; u2++)
        #pragma unroll
        for (int v = 0; v < 4; v++) o2acc2[u2][v] = 0ULL;
    #pragma unroll 4
    for (int s = 0; s < BT; ++s) {
        u64 a2[4], k2b[4];
        #pragma unroll
        for (int u2 = 0; u2 < 4; u2++)
            a2[u2] = pk2(Ss[(ty + 32 * u2) * PAD_S + s],
                         Ss[(ty + 32 * u2 + 16) * PAD_S + s]);
        #pragma unroll
        for (int v = 0; v < 4; v++) {
            float kk = Ks[s * PAD_D + tx + 16 * v];
            k2b[v] = pk2(kk, kk);
        }
        #pragma unroll
        for (int u2 = 0; u2 < 4; u2++)
            #pragma unroll
            for (int v = 0; v < 4; v++) fma2(o2acc2[u2][v], a2[u2], k2b[v]);
    }
    #pragma unroll 4
    for (int d = 0; d < DIM; ++d) {
        u64 a2[4], g2[4];
        #pragma unroll
        for (int u2 = 0; u2 < 4; u2++)
            a2[u2] = pk2(Qs[(ty + 32 * u2) * PAD_D + d],
                         Qs[(ty + 32 * u2 + 16) * PAD_D + d]);
        #pragma unroll
        for (int v = 0; v < 4; v++) {
            float gg = Gs[d * PAD_D + tx + 16 * v];
            g2[v] = pk2(gg, gg);
        }
        #pragma unroll
        for (int u2 = 0; u2 < 4; u2++)
            #pragma unroll
            for (int v = 0; v < 4; v++) fma2(o2acc2[u2][v], a2[u2], g2[v]);
    }
    __syncthreads();

    // ---- step 3: W = 2Q - O2 in place over Qs ----
    #pragma unroll
    for (int u2 = 0; u2 < 4; u2++)
        #pragma unroll
        for (int v = 0; v < 4; v++) {
            float lo, hi;
            upk2(lo, hi, o2acc2[u2][v]);
            int r0 = ty + 32 * u2, r1 = r0 + 16, c = tx + 16 * v;
            Qs[r0 * PAD_D + c] = 2.f * Qs[r0 * PAD_D + c] - lo;
            Qs[r1 * PAD_D + c] = 2.f * Qs[r1 * PAD_D + c] - hi;
        }
    __syncthreads();

    // ---- step 4: A = tril(W K_i^T) -> Ss ----
    {
        u64 acc2[8][4];
        #pragma unroll
        for (int u = 0; u < 8; u++)
            #pragma unroll
            for (int v2 = 0; v2 < 4; v2++) acc2[u][v2] = 0ULL;
        #pragma unroll 4
        for (int d = 0; d < DIM; ++d) {
            u64 w2[8], k2[4];
            #pragma unroll
            for (int u = 0; u < 8; u++) {
                float w = Qs[(ty + 16 * u) * PAD_D + d];
                w2[u] = pk2(w, w);
            }
            #pragma unroll
            for (int v2 = 0; v2 < 4; v2++)
                k2[v2] = pk2(Ks[(tx + 32 * v2) * PAD_D + d],
                             Ks[(tx + 32 * v2 + 16) * PAD_D + d]);
            #pragma unroll
            for (int u = 0; u < 8; u++)
                #pragma unroll
                for (int v2 = 0; v2 < 4; v2++) fma2(acc2[u][v2], w2[u], k2[v2]);
        }
        #pragma unroll
        for (int u = 0; u < 8; u++) {
            int r = ty + 16 * u;
            #pragma unroll
            for (int v2 = 0; v2 < 4; v2++) {
                float lo, hi;
                upk2(lo, hi, acc2[u][v2]);
                int c0 = tx + 32 * v2, c1 = c0 + 16;
                if (c0 > r) lo = 0.f;
                if (c1 > r) hi = 0.f;
                Ss[r * PAD_S + c0] = lo;
                Ss[r * PAD_S + c1] = hi;
            }
        }
    }
    __syncthreads();

    // ---- step 5: Out = A*V_i + W*Hsum ----
    u64 outacc2[4][4];
    #pragma unroll
    for (int u2 = 0; u2 < 4; u2++)
        #pragma unroll
        for (int v = 0; v < 4; v++) outacc2[u2][v] = 0ULL;
    #pragma unroll 4
    for (int s = 0; s < BT; ++s) {
        u64 a2[4], v2b[4];
        #pragma unroll
        for (int u2 = 0; u2 < 4; u2++)
            a2[u2] = pk2(Ss[(ty + 32 * u2) * PAD_S + s],
                         Ss[(ty + 32 * u2 + 16) * PAD_S + s]);
        #pragma unroll
        for (int v = 0; v < 4; v++) {
            float vv = Vs[s * PAD_D + tx + 16 * v];
            v2b[v] = pk2(vv, vv);
        }
        #pragma unroll
        for (int u2 = 0; u2 < 4; u2++)
            #pragma unroll
            for (int v = 0; v < 4; v++) fma2(outacc2[u2][v], a2[u2], v2b[v]);
    }
    #pragma unroll 4
    for (int d = 0; d < DIM; ++d) {
        u64 a2[4], h2[4];
        #pragma unroll
        for (int u2 = 0; u2 < 4; u2++)
            a2[u2] = pk2(Qs[(ty + 32 * u2) * PAD_D + d],
                         Qs[(ty + 32 * u2 + 16) * PAD_D + d]);
        #pragma unroll
        for (int v = 0; v < 4; v++) {
            float hh = Hs[d * PAD_D + tx + 16 * v];
            h2[v] = pk2(hh, hh);
        }
        #pragma unroll
        for (int u2 = 0; u2 < 4; u2++)
            #pragma unroll
            for (int v = 0; v < 4; v++) fma2(outacc2[u2][v], a2[u2], h2[v]);
    }

    #pragma unroll
    for (int u2 = 0; u2 < 4; u2++) {
        int r0 = ty + 32 * u2, r1 = r0 + 16;
        float* ob0 = out + ((long)b * SLEN + (t0 + r0)) * (NH * DIM) + (long)h * DIM;
        float* ob1 = out + ((long)b * SLEN + (t0 + r1)) * (NH * DIM) + (long)h * DIM;
        #pragma unroll
        for (int v = 0; v < 4; v++) {
            float lo, hi;
            upk2(lo, hi, outacc2[u2][v]);
            ob0[tx + 16 * v] = lo;
            ob1[tx + 16 * v] = hi;
        }
    }
}

extern "C" void kernel_launch(void* const* d_in, const int* in_sizes, int n_in,
                              void* d_out, int out_size) {
    (void)in_sizes; (void)n_in; (void)out_size;
    const float* qkv = (const float*)d_in[0];
    float* out = (float*)d_out;

    static bool configured = false;
    if (!configured) {
        cudaFuncSetAttribute(phaseA, cudaFuncAttributeMaxDynamicSharedMemorySize,
                             SMEM_A_BYTES);
        cudaFuncSetAttribute(phaseC, cudaFuncAttributeMaxDynamicSharedMemorySize,
                             SMEM_C_BYTES);
        configured = true;
    }

    dim3 gridA(NBLK, NH, NB);
    phaseA<<<gridA, NTHREADS, SMEM_A_BYTES>>>(qkv);
    phaseB<<<NB * NH, NTHREADS>>>();
    dim3 gridC(NBLK, NH, NB);
    phaseC<<<gridC, NTHREADS, SMEM_C_BYTES>>>(qkv, out);
}

// round 12
// speedup vs baseline: 5.7393x; 1.2070x over previous
#include <cuda_runtime.h>

// TTT_57174604644761: B=2, S=2048, H=16, D=64, fp32.
// Chunked O(S) form:  Gsum_i = sum_{j<i} K_j^T K_j,  Hsum_i = sum_{j<i} K_j^T V_j
//   O2_i  = Q_i*Gsum_i + tril(Q_i K_i^T) K_i
//   Out_i = W_i*Hsum_i + tril(W_i K_i^T) V_i,  W = 2Q - O2
// phaseA: per-block G,H (256 thr, ~87% FFMA2 roofline - unchanged)
// phaseB: exclusive prefix scan, widened grid (32x16 CTAs, 1 elem/thread)
// phaseC: local solve at 512 threads (4 warps/SMSP) to fill the FMA pipe.

#define SLEN 2048
#define NH   16
#define NB   2
#define DIM  64
#define BT   128
#define NBLK (SLEN / BT)      // 16
#define PAD_D 68
#define PAD_S 132
#define NTHREADS 256
#define CTHREADS 512

#define GH_ELEMS (NB * NH * NBLK * DIM * DIM)
__device__ float g_G[GH_ELEMS];
__device__ float g_H[GH_ELEMS];

typedef unsigned long long u64;

__device__ __forceinline__ u64 pk2(float lo, float hi) {
    u64 r;
    asm("mov.b64 %0, {%1, %2};"
        : "=l"(r) : "r"(__float_as_uint(lo)), "r"(__float_as_uint(hi)));
    return r;
}
__device__ __forceinline__ void upk2(float& lo, float& hi, u64 p) {
    unsigned ulo, uhi;
    asm("mov.b64 {%0, %1}, %2;" : "=r"(ulo), "=r"(uhi) : "l"(p));
    lo = __uint_as_float(ulo);
    hi = __uint_as_float(uhi);
}
__device__ __forceinline__ void fma2(u64& c, u64 a, u64 b) {
    asm("fma.rn.f32x2 %0, %1, %2, %0;" : "+l"(c) : "l"(a), "l"(b));
}

extern __shared__ float smem[];

#define SMEM_A_BYTES (2 * BT * PAD_D * 4)
#define SMEM_C_FLOATS (3 * BT * PAD_D + BT * PAD_S + 2 * DIM * PAD_D)
#define SMEM_C_BYTES (SMEM_C_FLOATS * 4)

// ============ PHASE A: G_j = K_j^T K_j, H_j = K_j^T V_j (unchanged) ============
__global__ __launch_bounds__(NTHREADS, 1)
void phaseA(const float* __restrict__ qkv) {
    const int j = blockIdx.x, h = blockIdx.y, b = blockIdx.z;
    const int tid = threadIdx.x, tx = tid & 15, ty = tid >> 4;

    float* Ks = smem;
    float* Vs = Ks + BT * PAD_D;

    const long rowstride = 3L * NH * DIM;
    const float* kbase = qkv + (long)b * SLEN * rowstride + (long)(1 * NH + h) * DIM;
    const float* vbase = qkv + (long)b * SLEN * rowstride + (long)(2 * NH + h) * DIM;

    for (int idx = tid; idx < 2 * BT * 16; idx += NTHREADS) {
        int half = idx >= BT * 16;
        int id2 = idx - half * BT * 16;
        int r = id2 >> 4, c4 = id2 & 15;
        const float* src = half ? vbase : kbase;
        float* dst = half ? Vs : Ks;
        *(float4*)(&dst[r * PAD_D + c4 * 4]) =
            *(const float4*)(src + (long)(j * BT + r) * rowstride + c4 * 4);
    }
    __syncthreads();

    u64 accG[4][2], accH[4][2];
    #pragma unroll
    for (int u = 0; u < 4; u++)
        #pragma unroll
        for (int p = 0; p < 2; p++) { accG[u][p] = 0ULL; accH[u][p] = 0ULL; }

    #pragma unroll 4
    for (int s = 0; s < BT; ++s) {
        u64 kr2[4], kc2[2], vc2[2];
        #pragma unroll
        for (int u = 0; u < 4; u++) {
            float kr = Ks[s * PAD_D + ty + 16 * u];
            kr2[u] = pk2(kr, kr);
        }
        #pragma unroll
        for (int p = 0; p < 2; p++) {
            kc2[p] = pk2(Ks[s * PAD_D + tx + 32 * p], Ks[s * PAD_D + tx + 32 * p + 16]);
            vc2[p] = pk2(Vs[s * PAD_D + tx + 32 * p], Vs[s * PAD_D + tx + 32 * p + 16]);
        }
        #pragma unroll
        for (int u = 0; u < 4; u++)
            #pragma unroll
            for (int p = 0; p < 2; p++) {
                fma2(accG[u][p], kr2[u], kc2[p]);
                fma2(accH[u][p], kr2[u], vc2[p]);
            }
    }

    const long base = ((long)(b * NH + h) * NBLK + j) * (DIM * DIM);
    #pragma unroll
    for (int u = 0; u < 4; u++) {
        int r = ty + 16 * u;
        #pragma unroll
        for (int p = 0; p < 2; p++) {
            float lo, hi;
            int c0 = tx + 32 * p, c1 = c0 + 16;
            upk2(lo, hi, accG[u][p]);
            g_G[base + r * DIM + c0] = lo;
            g_G[base + r * DIM + c1] = hi;
            upk2(lo, hi, accH[u][p]);
            g_H[base + r * DIM + c0] = lo;
            g_H[base + r * DIM + c1] = hi;
        }
    }
}

// ============ PHASE B: widened exclusive prefix scan ============
// grid (NB*NH, 16): each thread owns exactly one of 4096 elements.
__global__ __launch_bounds__(NTHREADS, 1)
void phaseB() {
    const long base = (long)blockIdx.x * NBLK * (DIM * DIM);
    const int e = blockIdx.y * NTHREADS + threadIdx.x;   // 0..4095
    float runG = 0.f, runH = 0.f;
    #pragma unroll
    for (int j = 0; j < NBLK; ++j) {
        long idx = base + (long)j * (DIM * DIM) + e;
        float g = g_G[idx]; g_G[idx] = runG; runG += g;
        float hv = g_H[idx]; g_H[idx] = runH; runH += hv;
    }
}

// ============ PHASE C: 512 threads, per (b,h,i) local solve ============
__global__ __launch_bounds__(CTHREADS, 1)
void phaseC(const float* __restrict__ qkv, float* __restrict__ out) {
    const int i = blockIdx.x, h = blockIdx.y, b = blockIdx.z;
    const int tid = threadIdx.x;
    const int tx = tid & 15;      // 0..15
    const int ty = tid >> 4;      // 0..31

    float* Qs = smem;                      // Q, then W = 2Q - O2
    float* Ks = Qs + BT * PAD_D;
    float* Vs = Ks + BT * PAD_D;
    float* Ss = Vs + BT * PAD_D;           // [BT][PAD_S]
    float* Gs = Ss + BT * PAD_S;           // [DIM][PAD_D]
    float* Hs = Gs + DIM * PAD_D;

    const long rowstride = 3L * NH * DIM;
    const float* qbase = qkv + (long)b * SLEN * rowstride + (long)(0 * NH + h) * DIM;
    const float* kbase = qkv + (long)b * SLEN * rowstride + (long)(1 * NH + h) * DIM;
    const float* vbase = qkv + (long)b * SLEN * rowstride + (long)(2 * NH + h) * DIM;
    const int t0 = i * BT;

    // ---- loads: Q_i, K_i, V_i ----
    for (int idx = tid; idx < 3 * BT * 16; idx += CTHREADS) {
        int which = idx / (BT * 16);
        int id2 = idx - which * (BT * 16);
        int r = id2 >> 4, c4 = id2 & 15;
        const float* src = (which == 0) ? qbase : (which == 1) ? kbase : vbase;
        float* dst = (which == 0) ? Qs : (which == 1) ? Ks : Vs;
        *(float4*)(&dst[r * PAD_D + c4 * 4]) =
            *(const float4*)(src + (long)(t0 + r) * rowstride + c4 * 4);
    }
    // ---- loads: Gsum_i, Hsum_i ----
    {
        const long gbase = ((long)(b * NH + h) * NBLK + i) * (DIM * DIM);
        for (int idx = tid; idx < 2 * DIM * 16; idx += CTHREADS) {
            int half = idx >= DIM * 16;
            int id2 = idx - half * DIM * 16;
            int r = id2 >> 4, c4 = id2 & 15;
            const float* src = half ? g_H : g_G;
            float* dst = half ? Hs : Gs;
            *(float4*)(&dst[r * PAD_D + c4 * 4]) =
                *(const float4*)(src + gbase + r * DIM + c4 * 4);
        }
    }
    __syncthreads();

    // ---- step 1: S1 = tril(Q K_i^T) -> Ss ----
    // rows r = ty+32u (u<4); col pairs (tx+32p, tx+32p+16), p<4
    {
        u64 acc2[4][4];
        #pragma unroll
        for (int u = 0; u < 4; u++)
            #pragma unroll
            for (int p = 0; p < 4; p++) acc2[u][p] = 0ULL;
        #pragma unroll 4
        for (int d = 0; d < DIM; ++d) {
            u64 q2[4], k2[4];
            #pragma unroll
            for (int u = 0; u < 4; u++) {
                float q = Qs[(ty + 32 * u) * PAD_D + d];
                q2[u] = pk2(q, q);
            }
            #pragma unroll
            for (int p = 0; p < 4; p++)
                k2[p] = pk2(Ks[(tx + 32 * p) * PAD_D + d],
                            Ks[(tx + 32 * p + 16) * PAD_D + d]);
            #pragma unroll
            for (int u = 0; u < 4; u++)
                #pragma unroll
                for (int p = 0; p < 4; p++) fma2(acc2[u][p], q2[u], k2[p]);
        }
        #pragma unroll
        for (int u = 0; u < 4; u++) {
            int r = ty + 32 * u;
            #pragma unroll
            for (int p = 0; p < 4; p++) {
                float lo, hi;
                upk2(lo, hi, acc2[u][p]);
                int c0 = tx + 32 * p, c1 = c0 + 16;
                if (c0 > r) lo = 0.f;
                if (c1 > r) hi = 0.f;
                Ss[r * PAD_S + c0] = lo;
                Ss[r * PAD_S + c1] = hi;
            }
        }
    }
    __syncthreads();

    // ---- step 2: O2 = S1*K_i + Q*Gsum ----
    // row pairs (ty+64a, ty+64a+32), a<2; cols 4tx+v, v<4
    u64 o2acc2[2][4];
    #pragma unroll
    for (int a = 0; a < 2; a++)
        #pragma unroll
        for (int v = 0; v < 4; v++) o2acc2[a][v] = 0ULL;
    #pragma unroll 4
    for (int s = 0; s < BT; ++s) {
        u64 a2[2], k2b[4];
        #pragma unroll
        for (int a = 0; a < 2; a++)
            a2[a] = pk2(Ss[(ty + 64 * a) * PAD_S + s],
                        Ss[(ty + 64 * a + 32) * PAD_S + s]);
        float4 kv = *(const float4*)(&Ks[s * PAD_D + 4 * tx]);
        k2b[0] = pk2(kv.x, kv.x); k2b[1] = pk2(kv.y, kv.y);
        k2b[2] = pk2(kv.z, kv.z); k2b[3] = pk2(kv.w, kv.w);
        #pragma unroll
        for (int a = 0; a < 2; a++)
            #pragma unroll
            for (int v = 0; v < 4; v++) fma2(o2acc2[a][v], a2[a], k2b[v]);
    }
    #pragma unroll 4
    for (int d = 0; d < DIM; ++d) {
        u64 a2[2], g2[4];
        #pragma unroll
        for (int a = 0; a < 2; a++)
            a2[a] = pk2(Qs[(ty + 64 * a) * PAD_D + d],
                        Qs[(ty + 64 * a + 32) * PAD_D + d]);
        float4 gv = *(const float4*)(&Gs[d * PAD_D + 4 * tx]);
        g2[0] = pk2(gv.x, gv.x); g2[1] = pk2(gv.y, gv.y);
        g2[2] = pk2(gv.z, gv.z); g2[3] = pk2(gv.w, gv.w);
        #pragma unroll
        for (int a = 0; a < 2; a++)
            #pragma unroll
            for (int v = 0; v < 4; v++) fma2(o2acc2[a][v], a2[a], g2[v]);
    }
    __syncthreads();

    // ---- step 3: W = 2Q - O2 in place over Qs ----
    #pragma unroll
    for (int a = 0; a < 2; a++)
        #pragma unroll
        for (int v = 0; v < 4; v++) {
            float lo, hi;
            upk2(lo, hi, o2acc2[a][v]);
            int r0 = ty + 64 * a, r1 = r0 + 32, c = 4 * tx + v;
            Qs[r0 * PAD_D + c] = 2.f * Qs[r0 * PAD_D + c] - lo;
            Qs[r1 * PAD_D + c] = 2.f * Qs[r1 * PAD_D + c] - hi;
        }
    __syncthreads();

    // ---- step 4: A = tril(W K_i^T) -> Ss ----
    {
        u64 acc2[4][4];
        #pragma unroll
        for (int u = 0; u < 4; u++)
            #pragma unroll
            for (int p = 0; p < 4; p++) acc2[u][p] = 0ULL;
        #pragma unroll 4
        for (int d = 0; d < DIM; ++d) {
            u64 w2[4], k2[4];
            #pragma unroll
            for (int u = 0; u < 4; u++) {
                float w = Qs[(ty + 32 * u) * PAD_D + d];
                w2[u] = pk2(w, w);
            }
            #pragma unroll
            for (int p = 0; p < 4; p++)
                k2[p] = pk2(Ks[(tx + 32 * p) * PAD_D + d],
                            Ks[(tx + 32 * p + 16) * PAD_D + d]);
            #pragma unroll
            for (int u = 0; u < 4; u++)
                #pragma unroll
                for (int p = 0; p < 4; p++) fma2(acc2[u][p], w2[u], k2[p]);
        }
        #pragma unroll
        for (int u = 0; u < 4; u++) {
            int r = ty + 32 * u;
            #pragma unroll
            for (int p = 0; p < 4; p++) {
                float lo, hi;
                upk2(lo, hi, acc2[u][p]);
                int c0 = tx + 32 * p, c1 = c0 + 16;
                if (c0 > r) lo = 0.f;
                if (c1 > r) hi = 0.f;
                Ss[r * PAD_S + c0] = lo;
                Ss[r * PAD_S + c1] = hi;
            }
        }
    }
    __syncthreads();

    // ---- step 5: Out = A*V_i + W*Hsum ----
    u64 outacc2[2][4];
    #pragma unroll
    for (int a = 0; a < 2; a++)
        #pragma unroll
        for (int v = 0; v < 4; v++) outacc2[a][v] = 0ULL;
    #pragma unroll 4
    for (int s = 0; s < BT; ++s) {
        u64 a2[2], v2b[4];
        #pragma unroll
        for (int a = 0; a < 2; a++)
            a2[a] = pk2(Ss[(ty + 64 * a) * PAD_S + s],
                        Ss[(ty + 64 * a + 32) * PAD_S + s]);
        float4 vv = *(const float4*)(&Vs[s * PAD_D + 4 * tx]);
        v2b[0] = pk2(vv.x, vv.x); v2b[1] = pk2(vv.y, vv.y);
        v2b[2] = pk2(vv.z, vv.z); v2b[3] = pk2(vv.w, vv.w);
        #pragma unroll
        for (int a = 0; a < 2; a++)
            #pragma unroll
            for (int v = 0; v < 4; v++) fma2(outacc2[a][v], a2[a], v2b[v]);
    }
    #pragma unroll 4
    for (int d = 0; d < DIM; ++d) {
        u64 a2[2], h2[4];
        #pragma unroll
        for (int a = 0; a < 2; a++)
            a2[a] = pk2(Qs[(ty + 64 * a) * PAD_D + d],
                        Qs[(ty + 64 * a + 32) * PAD_D + d]);
        float4 hv = *(const float4*)(&Hs[d * PAD_D + 4 * tx]);
        h2[0] = pk2(hv.x, hv.x); h2[1] = pk2(hv.y, hv.y);
        h2[2] = pk2(hv.z, hv.z); h2[3] = pk2(hv.w, hv.w);
        #pragma unroll
        for (int a = 0; a < 2; a++)
            #pragma unroll
            for (int v = 0; v < 4; v++) fma2(outacc2[a][v], a2[a], h2[v]);
    }

    // ---- write Out: rows (ty+64a, ty+64a+32), cols 4tx..4tx+3 (float4) ----
    #pragma unroll
    for (int a = 0; a < 2; a++) {
        int r0 = ty + 64 * a, r1 = r0 + 32;
        float lo0, hi0, lo1, hi1, lo2, hi2, lo3, hi3;
        upk2(lo0, hi0, outacc2[a][0]);
        upk2(lo1, hi1, outacc2[a][1]);
        upk2(lo2, hi2, outacc2[a][2]);
        upk2(lo3, hi3, outacc2[a][3]);
        float4 w0 = make_float4(lo0, lo1, lo2, lo3);
        float4 w1 = make_float4(hi0, hi1, hi2, hi3);
        float* ob0 = out + ((long)b * SLEN + (t0 + r0)) * (NH * DIM) + (long)h * DIM;
        float* ob1 = out + ((long)b * SLEN + (t0 + r1)) * (NH * DIM) + (long)h * DIM;
        *(float4*)(ob0 + 4 * tx) = w0;
        *(float4*)(ob1 + 4 * tx) = w1;
    }
}

extern "C" void kernel_launch(void* const* d_in, const int* in_sizes, int n_in,
                              void* d_out, int out_size) {
    (void)in_sizes; (void)n_in; (void)out_size;
    const float* qkv = (const float*)d_in[0];
    float* out = (float*)d_out;

    static bool configured = false;
    if (!configured) {
        cudaFuncSetAttribute(phaseA, cudaFuncAttributeMaxDynamicSharedMemorySize,
                             SMEM_A_BYTES);
        cudaFuncSetAttribute(phaseC, cudaFuncAttributeMaxDynamicSharedMemorySize,
                             SMEM_C_BYTES);
        configured = true;
    }

    dim3 gridA(NBLK, NH, NB);
    phaseA<<<gridA, NTHREADS, SMEM_A_BYTES>>>(qkv);
    dim3 gridB(NB * NH, (DIM * DIM) / NTHREADS);   // (32, 16)
    phaseB<<<gridB, NTHREADS>>>();
    dim3 gridC(NBLK, NH, NB);
    phaseC<<<gridC, CTHREADS, SMEM_C_BYTES>>>(qkv, out);
}